// round 13
// baseline (speedup 1.0000x reference)
#include <cuda_runtime.h>
#include <cuda_bf16.h>
#include <cstdint>
#include <math.h>

#define Bsz 512
#define Ssz 256
#define Esz 256
#define Hsz 512
#define Gsz 1536
#define Lsz 8
#define MROWS (Ssz * Bsz)
#define NCTA 128

// ---------------- device-global scratch (no runtime alloc) ------------------
__device__ __align__(16) float g_gi[(size_t)MROWS * Gsz];
__device__ __align__(16) float g_hf[Bsz * Hsz];          // final h only
__device__ __align__(16) __nv_bfloat16 g_hb_hi[2][Bsz * Hsz];
__device__ __align__(16) __nv_bfloat16 g_hb_lo[2][Bsz * Hsz];
__device__ __align__(16) __nv_bfloat16 g_x_hi[(size_t)MROWS * Esz];
__device__ __align__(16) __nv_bfloat16 g_x_lo[(size_t)MROWS * Esz];
__device__ __align__(16) __nv_bfloat16 g_whh_hi[Gsz * Hsz];
__device__ __align__(16) __nv_bfloat16 g_whh_lo[Gsz * Hsz];
__device__ __align__(16) __nv_bfloat16 g_wih_hi[Gsz * Esz];
__device__ __align__(16) __nv_bfloat16 g_wih_lo[Gsz * Esz];
// counter per (b-group bx 0-3, octet oct 0-3): producers jy in [oct*8, oct*8+8)
// each add 1 per finished step. 128B apart.
__device__ unsigned int g_bars[512];

// ---------------- PTX helpers (base-target only) -----------------------------
__device__ __forceinline__ uint32_t smem_u32(const void* p) {
    uint32_t a;
    asm("{ .reg .u64 t; cvta.to.shared.u64 t, %1; cvt.u32.u64 %0, t; }" : "=r"(a) : "l"(p));
    return a;
}
__device__ __forceinline__ void cp16(uint32_t dst, const void* src) {
    asm volatile("cp.async.cg.shared.global [%0], [%1], 16;" :: "r"(dst), "l"(src));
}
#define CP_COMMIT() asm volatile("cp.async.commit_group;" ::: "memory")
#define CP_WAIT(n)  asm volatile("cp.async.wait_group %0;" :: "n"(n) : "memory")

#define LDMX4(r, addr) \
    asm volatile("ldmatrix.sync.aligned.m8n8.x4.shared.b16 {%0,%1,%2,%3}, [%4];" \
        : "=r"((r)[0]), "=r"((r)[1]), "=r"((r)[2]), "=r"((r)[3]) : "r"(addr))

#define MMA_BF16(c, a, b0, b1) \
    asm volatile("mma.sync.aligned.m16n8k16.row.col.f32.bf16.bf16.f32 " \
        "{%0,%1,%2,%3}, {%4,%5,%6,%7}, {%8,%9}, {%0,%1,%2,%3};" \
        : "+f"((c)[0]), "+f"((c)[1]), "+f"((c)[2]), "+f"((c)[3]) \
        : "r"((a)[0]), "r"((a)[1]), "r"((a)[2]), "r"((a)[3]), "r"(b0), "r"(b1))

__device__ __forceinline__ void poll_cnt(const unsigned int* p, unsigned int tgt) {
    if (tgt == 0) return;
    unsigned int v;
    do {
        asm volatile("ld.acquire.gpu.u32 %0, [%1];" : "=r"(v) : "l"(p));
    } while (v < tgt);
}

// ---------------- split helpers ----------------------------------------------
__device__ __forceinline__ void split2(float v, __nv_bfloat16& h, __nv_bfloat16& l) {
    h = __float2bfloat16_rn(v);
    l = __float2bfloat16_rn(v - __bfloat162float(h));
}
__device__ __forceinline__ void split_store4(float4 v, __nv_bfloat16* dh, __nv_bfloat16* dl) {
    __nv_bfloat16 h0,l0,h1,l1,h2,l2,h3,l3;
    split2(v.x,h0,l0); split2(v.y,h1,l1); split2(v.z,h2,l2); split2(v.w,h3,l3);
    __nv_bfloat162 p;
    p.x=h0; p.y=h1; ((__nv_bfloat162*)dh)[0]=p;
    p.x=h2; p.y=h3; ((__nv_bfloat162*)dh)[1]=p;
    p.x=l0; p.y=l1; ((__nv_bfloat162*)dl)[0]=p;
    p.x=l2; p.y=l3; ((__nv_bfloat162*)dl)[1]=p;
}

// tiny no-op kernels: keep the ncu capture window on gru_persist_kernel
__global__ void noop_kernel() {}

// ---------------------------------------------------------------------------
// prep: x split, W_hh split, W_ih split, h0/bars init, one launch
// ---------------------------------------------------------------------------
__global__ void prep_kernel(const float* __restrict__ x,
                            const float* __restrict__ W_hh,
                            const float* __restrict__ W_ih) {
    int blk = blockIdx.x, tid = threadIdx.x;
    if (blk < 32768) {
        size_t t = (size_t)blk * 256 + tid;
        size_t m = t >> 6;
        int e4 = (int)(t & 63) << 2;
        int s = (int)(m >> 9), b = (int)(m & 511);
        float4 v = *(const float4*)(x + ((size_t)b * Ssz + s) * Esz + e4);
        split_store4(v, g_x_hi + m * Esz + e4, g_x_lo + m * Esz + e4);
    } else if (blk < 33536) {
        int t = (blk - 32768) * 256 + tid;
        float4 v = *(const float4*)(W_hh + (size_t)t * 4);
        split_store4(v, g_whh_hi + (size_t)t * 4, g_whh_lo + (size_t)t * 4);
    } else if (blk < 33920) {
        int t = (blk - 33536) * 256 + tid;
        float4 v = *(const float4*)(W_ih + (size_t)t * 4);
        split_store4(v, g_wih_hi + (size_t)t * 4, g_wih_lo + (size_t)t * 4);
    } else {
        int i = (blk - 33920) * 256 + tid;   // < Bsz*Hsz/2
        __nv_bfloat162 z;
        z.x = __float2bfloat16_rn(0.0f); z.y = z.x;
        ((__nv_bfloat162*)g_hb_hi[0])[i] = z;
        ((__nv_bfloat162*)g_hb_lo[0])[i] = z;
        if (i < 512) g_bars[i] = 0u;
    }
}

// ---------------------------------------------------------------------------
// gi GEMM (HMMA): R7 version (single 72KB buffer, 3 CTAs/SM). Known-good.
// ---------------------------------------------------------------------------
#define GI_SMEM 73728
#define GA_HI 0
#define GA_LO 18432
#define GB_HI 36864
#define GB_LO 55296

__global__ void __launch_bounds__(256) gi_mma_kernel(const float* __restrict__ b_ih) {
    extern __shared__ __align__(16) char dsm[];
    __shared__ float s_bias[128];
    uint32_t sbase = smem_u32(dsm);
    int tid = threadIdx.x, wid = tid >> 5, lane = tid & 31;
    int n0 = blockIdx.x * 128;
    int m0 = blockIdx.y * 128;
    if (tid < 128) s_bias[tid] = b_ih[n0 + tid];

    int m_warp = (wid & 1) * 64;
    int n_warp = (wid >> 1) * 32;

    float acc[4][4][4];
#pragma unroll
    for (int mi = 0; mi < 4; mi++)
#pragma unroll
        for (int ni = 0; ni < 4; ni++)
#pragma unroll
            for (int e = 0; e < 4; e++) acc[mi][ni][e] = 0.0f;

    for (int c = 0; c < 4; c++) {
        int k0 = c * 64;
        for (int i = tid; i < 4096; i += 256) {
            const __nv_bfloat16* sp;
            uint32_t dst;
            int half = (i >> 10) & 1;
            int idx = i & 1023;
            int row = idx >> 3, seg = idx & 7;
            if (i < 2048) {
                sp = (half ? g_x_lo : g_x_hi) + ((size_t)(m0 + row)) * Esz + k0 + seg * 8;
                dst = sbase + (half ? GA_LO : GA_HI) + (uint32_t)(row * 144 + seg * 16);
            } else {
                sp = (half ? g_wih_lo : g_wih_hi) + ((size_t)(n0 + row)) * Esz + k0 + seg * 8;
                dst = sbase + (half ? GB_LO : GB_HI) + (uint32_t)(row * 144 + seg * 16);
            }
            cp16(dst, sp);
        }
        CP_COMMIT();
        CP_WAIT(0);
        __syncthreads();
#pragma unroll
        for (int kk = 0; kk < 4; kk++) {
            int kb = kk * 32;
            uint32_t fa[2][4][4];
#pragma unroll
            for (int mi = 0; mi < 4; mi++) {
                uint32_t arow = (uint32_t)(m_warp + mi * 16 + (lane & 15));
                uint32_t aoff = arow * 144 + kb + ((lane >> 4) << 4);
                LDMX4(fa[0][mi], sbase + GA_HI + aoff);
                LDMX4(fa[1][mi], sbase + GA_LO + aoff);
            }
            uint32_t fb[2][2][4];
#pragma unroll
            for (int p = 0; p < 2; p++) {
                uint32_t brow = (uint32_t)(n_warp + p * 16 + (lane & 7) + ((lane >> 4) << 3));
                uint32_t boff = brow * 144 + kb + (((lane >> 3) & 1) << 4);
                LDMX4(fb[0][p], sbase + GB_HI + boff);
                LDMX4(fb[1][p], sbase + GB_LO + boff);
            }
#pragma unroll
            for (int t = 0; t < 3; t++) {
                int sa = (t == 2) ? 1 : 0, sb = (t == 1) ? 1 : 0;
#pragma unroll
                for (int mi = 0; mi < 4; mi++)
#pragma unroll
                    for (int ni = 0; ni < 4; ni++)
                        MMA_BF16(acc[mi][ni], fa[sa][mi],
                                 fb[sb][ni >> 1][(ni & 1) * 2],
                                 fb[sb][ni >> 1][(ni & 1) * 2 + 1]);
            }
        }
        __syncthreads();
    }

#pragma unroll
    for (int mi = 0; mi < 4; mi++) {
        int m = m0 + m_warp + mi * 16 + (lane >> 2);
#pragma unroll
        for (int ni = 0; ni < 4; ni++) {
            int nl = n_warp + ni * 8 + (lane & 3) * 2;
            float2 v0 = make_float2(acc[mi][ni][0] + s_bias[nl],
                                    acc[mi][ni][1] + s_bias[nl + 1]);
            float2 v1 = make_float2(acc[mi][ni][2] + s_bias[nl],
                                    acc[mi][ni][3] + s_bias[nl + 1]);
            *(float2*)(g_gi + (size_t)m * Gsz + n0 + nl) = v0;
            *(float2*)(g_gi + (size_t)(m + 8) * Gsz + n0 + nl) = v1;
        }
    }
}

// ---------------------------------------------------------------------------
// Persistent GRU recurrence, R13 retile:
//   128 CTAs = 4 b-groups (128 batch rows) x 32 j-tiles (16 hidden cols).
//   W tile: 48 rows x 512 K x 2 splits = 96KB resident (halved).
//   h: 4 chunks of 128 K-cols (64KB each), double-buffered (2x64KB).
//   8 M-warps x m16, each covering all n48; 6 barriers/step vs 10.
//   K accumulation order identical to R11 -> rel_err must be bit-identical.
// smem map: W hi [0,48K) | W lo [48K,96K) | hbuf0 [96K,160K) | hbuf1 [160K,224K)
//   W: sub-chunk sc(0-7) stride 6144; row(0-47)*128; unit u XOR (row&7).
//   h buf: split stride 32768; sub sc2(0-1) stride 16384; row(0-127)*128.
// ---------------------------------------------------------------------------
#define WSPLIT 49152
#define WSUB   6144
#define WTOT   98304
#define HBUF   65536
#define HSPLIT 32768
#define HSUB   16384
#define PS_SMEM (WTOT + 2 * HBUF)   // 229376

__device__ __forceinline__ void prefetch_gi(int s, int brow0, int brow1, int jcol,
                                            float2 pg[3][2][2]) {
    const float* base = g_gi + (size_t)s * Bsz * Gsz;
#pragma unroll
    for (int g = 0; g < 3; g++) {
#pragma unroll
        for (int ri = 0; ri < 2; ri++) {
            const float* p = base + (size_t)(ri ? brow1 : brow0) * Gsz + g * Hsz + jcol;
            pg[g][ri][0] = *(const float2*)(p);
            pg[g][ri][1] = *(const float2*)(p + 8);
        }
    }
}

__global__ void __launch_bounds__(256) gru_persist_kernel(
    const float* __restrict__ b_hh, const float* __restrict__ W_out,
    const float* __restrict__ b_out, float* __restrict__ out) {
    extern __shared__ __align__(16) char dsm[];
    __shared__ float s_bhh[48];
    uint32_t sbase = smem_u32(dsm);
    int tid = threadIdx.x, wid = tid >> 5, lane = tid & 31;
    int bx = blockIdx.x >> 5, jy = blockIdx.x & 31;
    int b0 = bx * 128, j0 = jy * 16;
    if (tid < 48) s_bhh[tid] = b_hh[(tid >> 4) * Hsz + j0 + (tid & 15)];

    // ---- resident W_hh tile: 48 rows x 512 cols x 2 splits, XOR swizzle ----
    // 6144 16B units: p(2) x sc(8) x row(48) x u(8)
    for (int i = tid; i < 6144; i += 256) {
        int p = i / 3072;
        int r2 = i - p * 3072;
        int sc = r2 / 384;
        int r3 = r2 - sc * 384;
        int row = r3 >> 3, u = r3 & 7;
        int g = row >> 4, jr = row & 15;
        const __nv_bfloat16* sp = (p ? g_whh_lo : g_whh_hi) +
            ((size_t)(g * Hsz + j0 + jr)) * Hsz + sc * 64 + u * 8;
        uint32_t dst = sbase + (uint32_t)(p * WSPLIT + sc * WSUB + row * 128 +
                                          ((u ^ (row & 7)) << 4));
        cp16(dst, sp);
    }
    CP_COMMIT();
    CP_WAIT(0);
    __syncthreads();

    const int m_warp = wid * 16;            // 8 warps x 16 rows = 128
    const int q2 = (lane & 3) * 2;
    const int r0 = m_warp + (lane >> 2);
    const int brow0 = b0 + r0, brow1 = b0 + r0 + 8;
    const int jcol = j0 + q2;
    unsigned int* mybar = &g_bars[(bx * 4 + (jy >> 3)) * 32];

    // kk-invariant LDSM address parts
    const uint32_t arow = (uint32_t)(m_warp + (lane & 15));
    const uint32_t a_ub = (uint32_t)(lane >> 4);
    const uint32_t a_rowoff = arow * 128;
    const uint32_t a_rx = arow & 7;
    uint32_t b_rowoff[3], b_rx[3];
#pragma unroll
    for (int pp = 0; pp < 3; pp++) {
        uint32_t brow = (uint32_t)(pp * 16 + (lane & 7) + ((lane >> 4) << 3));
        b_rowoff[pp] = brow * 128;
        b_rx[pp] = brow & 7;
    }
    const uint32_t b_ub = (uint32_t)((lane >> 3) & 1);

    float2 hp[2][2];
#pragma unroll
    for (int ri = 0; ri < 2; ri++)
#pragma unroll
        for (int su = 0; su < 2; su++) hp[ri][su] = make_float2(0.0f, 0.0f);

    float2 pg[3][2][2];
    prefetch_gi(0, brow0, brow1, jcol, pg);

    for (int s = 0; s < Ssz; s++) {
        int pin = s & 1, pout = pin ^ 1;
        const __nv_bfloat16* ah = g_hb_hi[pin];
        const __nv_bfloat16* al = g_hb_lo[pin];

        // gate the whole step: 4 octet counters polled in parallel by 4 threads
        if (tid < 4) poll_cnt(&g_bars[(bx * 4 + tid) * 32], 8u * (unsigned int)s);
        __syncthreads();

        auto issue_h = [&](int c, int q) {
            uint32_t base = sbase + WTOT + (uint32_t)q * HBUF;
            // 4096 units: p(2) x sc2(2) x row(128) x u(8); 16 per thread
            for (int i = tid; i < 4096; i += 256) {
                int p = i >> 11;
                int r2 = i & 2047;
                int sc2 = r2 >> 10;
                int r3 = r2 & 1023;
                int row = r3 >> 3, u = r3 & 7;
                const __nv_bfloat16* sp = (p ? al : ah) +
                    ((size_t)(b0 + row)) * Hsz + c * 128 + sc2 * 64 + u * 8;
                uint32_t dst = base + (uint32_t)(p * HSPLIT + sc2 * HSUB + row * 128 +
                                                 ((u ^ (row & 7)) << 4));
                cp16(dst, sp);
            }
            CP_COMMIT();
        };

        float acc[6][4];
#pragma unroll
        for (int ni = 0; ni < 6; ni++)
#pragma unroll
            for (int e = 0; e < 4; e++) acc[ni][e] = 0.0f;

        issue_h(0, 0);
        for (int c = 0; c < 4; c++) {
            int q = c & 1;
            if (c < 3) { issue_h(c + 1, q ^ 1); CP_WAIT(1); } else { CP_WAIT(0); }
            __syncthreads();
            uint32_t hb = sbase + WTOT + (uint32_t)q * HBUF;

            uint32_t fa[2][2][4];
            uint32_t fb[2][2][3][4];
            auto load_frags = [&](int kk, int fq) {
                uint32_t sub = (uint32_t)(kk >> 2);
                uint32_t ua = (uint32_t)((kk & 3) * 2) + a_ub;
                uint32_t offa = sub * HSUB + a_rowoff + ((ua ^ a_rx) << 4);
                LDMX4(fa[fq][0], hb + offa);
                LDMX4(fa[fq][1], hb + HSPLIT + offa);
                uint32_t wsub = sbase + (uint32_t)((c * 2 + (int)sub) * WSUB);
                uint32_t ub = (uint32_t)((kk & 3) * 2) + b_ub;
#pragma unroll
                for (int pp = 0; pp < 3; pp++) {
                    uint32_t offb = b_rowoff[pp] + ((ub ^ b_rx[pp]) << 4);
                    LDMX4(fb[fq][0][pp], wsub + offb);
                    LDMX4(fb[fq][1][pp], wsub + WSPLIT + offb);
                }
            };

            load_frags(0, 0);
#pragma unroll
            for (int kk = 0; kk < 8; kk++) {
                int fq = kk & 1;
                if (kk < 7) load_frags(kk + 1, fq ^ 1);
#pragma unroll
                for (int t = 0; t < 3; t++) {
                    int sa = (t == 2) ? 1 : 0, sb = (t == 1) ? 1 : 0;
#pragma unroll
                    for (int ni = 0; ni < 6; ni++)
                        MMA_BF16(acc[ni], fa[fq][sa],
                                 fb[fq][sb][ni >> 1][(ni & 1) * 2],
                                 fb[fq][sb][ni >> 1][(ni & 1) * 2 + 1]);
                }
            }
        }

        // ---- register-resident GRU epilogue ----
        __nv_bfloat16* hho = g_hb_hi[pout];
        __nv_bfloat16* hlo = g_hb_lo[pout];
#pragma unroll
        for (int ri = 0; ri < 2; ri++) {
            int b = ri ? brow1 : brow0;
#pragma unroll
            for (int su = 0; su < 2; su++) {
                float hv[2];
#pragma unroll
                for (int e = 0; e < 2; e++) {
                    float dr = acc[0 * 2 + su][ri * 2 + e] + s_bhh[su * 8 + q2 + e];
                    float dz = acc[1 * 2 + su][ri * 2 + e] + s_bhh[16 + su * 8 + q2 + e];
                    float dn = acc[2 * 2 + su][ri * 2 + e] + s_bhh[32 + su * 8 + q2 + e];
                    float gi_r = e ? pg[0][ri][su].y : pg[0][ri][su].x;
                    float gi_z = e ? pg[1][ri][su].y : pg[1][ri][su].x;
                    float gi_n = e ? pg[2][ri][su].y : pg[2][ri][su].x;
                    float hprev = e ? hp[ri][su].y : hp[ri][su].x;
                    float r = __fdividef(1.0f, 1.0f + __expf(-(gi_r + dr)));
                    float z = __fdividef(1.0f, 1.0f + __expf(-(gi_z + dz)));
                    float n = tanhf(gi_n + r * dn);
                    hv[e] = (1.0f - z) * n + z * hprev;
                }
                hp[ri][su] = make_float2(hv[0], hv[1]);
                int j = jcol + su * 8;
                __nv_bfloat16 h0, l0, h1, l1;
                split2(hv[0], h0, l0);
                split2(hv[1], h1, l1);
                __nv_bfloat162 ph, pl;
                ph.x = h0; ph.y = h1;
                pl.x = l0; pl.y = l1;
                *(__nv_bfloat162*)(hho + (size_t)b * Hsz + j) = ph;
                *(__nv_bfloat162*)(hlo + (size_t)b * Hsz + j) = pl;
                if (s == Ssz - 1)
                    *(float2*)(g_hf + (size_t)b * Hsz + j) = make_float2(hv[0], hv[1]);
            }
        }

        // ---- publish, then prefetch next gi ----
        __syncthreads();
        if (tid == 0) {
            asm volatile("red.release.gpu.global.add.u32 [%0], %1;"
                         :: "l"(mybar), "r"(1u) : "memory");
        }
        if (s + 1 < Ssz) prefetch_gi(s + 1, brow0, brow1, jcol, pg);
    }

    // ---- fused head: jy==0 CTAs (4), rows b0..b0+127, after group finishes ----
    if (jy == 0) {
        if (tid < 4) poll_cnt(&g_bars[(bx * 4 + tid) * 32], 8u * (unsigned int)Ssz);
        __syncthreads();
#pragma unroll 1
        for (int rr = 0; rr < 16; rr++) {
            int b = b0 + wid * 16 + rr;
            const float* h = g_hf + (size_t)b * Hsz;
            float a8[Lsz];
#pragma unroll
            for (int l = 0; l < Lsz; l++) a8[l] = 0.0f;
            for (int j = lane; j < Hsz; j += 32) {
                float hv = h[j];
#pragma unroll
                for (int l = 0; l < Lsz; l++) a8[l] += hv * W_out[l * Hsz + j];
            }
#pragma unroll
            for (int l = 0; l < Lsz; l++)
#pragma unroll
                for (int o = 16; o > 0; o >>= 1)
                    a8[l] += __shfl_xor_sync(0xffffffff, a8[l], o);
            if (lane == 0) {
                float logits[Lsz], mx = -1e30f, sum = 0.0f;
#pragma unroll
                for (int l = 0; l < Lsz; l++) {
                    logits[l] = a8[l] + b_out[l];
                    mx = fmaxf(mx, logits[l]);
                }
#pragma unroll
                for (int l = 0; l < Lsz; l++) {
                    logits[l] = expf(logits[l] - mx);
                    sum += logits[l];
                }
                float inv = 1.0f / sum;
#pragma unroll
                for (int l = 0; l < Lsz; l++)
                    out[(size_t)b * Lsz + l] = logits[l] * inv;
            }
        }
    }
}

// ---------------------------------------------------------------------------
extern "C" void kernel_launch(void* const* d_in, const int* in_sizes, int n_in,
                              void* d_out, int out_size) {
    const float* x     = (const float*)d_in[0];
    const float* W_ih  = (const float*)d_in[1];
    const float* W_hh  = (const float*)d_in[2];
    const float* b_ih  = (const float*)d_in[3];
    const float* b_hh  = (const float*)d_in[4];
    const float* W_out = (const float*)d_in[5];
    const float* b_out = (const float*)d_in[6];
    float* out = (float*)d_out;

    cudaFuncSetAttribute(gi_mma_kernel, cudaFuncAttributeMaxDynamicSharedMemorySize, GI_SMEM);
    cudaFuncSetAttribute(gru_persist_kernel, cudaFuncAttributeMaxDynamicSharedMemorySize, PS_SMEM);

    // identical launch sequence so the ncu window stays on gru
    noop_kernel<<<1, 32>>>();
    prep_kernel<<<34432, 256>>>(x, W_hh, W_ih);
    gi_mma_kernel<<<dim3(Gsz / 128, MROWS / 128), 256, GI_SMEM>>>(b_ih);
    gru_persist_kernel<<<NCTA, 256, PS_SMEM>>>(b_hh, W_out, b_out, out);
    noop_kernel<<<1, 32>>>();
    noop_kernel<<<1, 32>>>();
}

// round 14
// speedup vs baseline: 1.1356x; 1.1356x over previous
#include <cuda_runtime.h>
#include <cuda_bf16.h>
#include <cstdint>
#include <math.h>

#define Bsz 512
#define Ssz 256
#define Esz 256
#define Hsz 512
#define Gsz 1536
#define Lsz 8
#define MROWS (Ssz * Bsz)
#define NCTA 128

// ---------------- device-global scratch (no runtime alloc) ------------------
__device__ __align__(16) float g_gi[(size_t)MROWS * Gsz];
__device__ __align__(16) float g_hf[Bsz * Hsz];          // final h only
__device__ __align__(16) __nv_bfloat16 g_hb_hi[2][Bsz * Hsz];
__device__ __align__(16) __nv_bfloat16 g_hb_lo[2][Bsz * Hsz];
__device__ __align__(16) __nv_bfloat16 g_x_hi[(size_t)MROWS * Esz];
__device__ __align__(16) __nv_bfloat16 g_x_lo[(size_t)MROWS * Esz];
__device__ __align__(16) __nv_bfloat16 g_whh_hi[Gsz * Hsz];
__device__ __align__(16) __nv_bfloat16 g_whh_lo[Gsz * Hsz];
__device__ __align__(16) __nv_bfloat16 g_wih_hi[Gsz * Esz];
__device__ __align__(16) __nv_bfloat16 g_wih_lo[Gsz * Esz];
__device__ unsigned int g_bars[8 * 32];   // per-b-group counters, 128B apart

// ---------------- PTX helpers (base-target only) -----------------------------
__device__ __forceinline__ uint32_t smem_u32(const void* p) {
    uint32_t a;
    asm("{ .reg .u64 t; cvta.to.shared.u64 t, %1; cvt.u32.u64 %0, t; }" : "=r"(a) : "l"(p));
    return a;
}
__device__ __forceinline__ void cp16(uint32_t dst, const void* src) {
    asm volatile("cp.async.cg.shared.global [%0], [%1], 16;" :: "r"(dst), "l"(src));
}
#define CP_COMMIT() asm volatile("cp.async.commit_group;" ::: "memory")
#define CP_WAIT(n)  asm volatile("cp.async.wait_group %0;" :: "n"(n) : "memory")

#define LDMX4(r, addr) \
    asm volatile("ldmatrix.sync.aligned.m8n8.x4.shared.b16 {%0,%1,%2,%3}, [%4];" \
        : "=r"((r)[0]), "=r"((r)[1]), "=r"((r)[2]), "=r"((r)[3]) : "r"(addr))

#define MMA_BF16(c, a, b0, b1) \
    asm volatile("mma.sync.aligned.m16n8k16.row.col.f32.bf16.bf16.f32 " \
        "{%0,%1,%2,%3}, {%4,%5,%6,%7}, {%8,%9}, {%0,%1,%2,%3};" \
        : "+f"((c)[0]), "+f"((c)[1]), "+f"((c)[2]), "+f"((c)[3]) \
        : "r"((a)[0]), "r"((a)[1]), "r"((a)[2]), "r"((a)[3]), "r"(b0), "r"(b1))

// ---------------- split helpers ----------------------------------------------
__device__ __forceinline__ void split2(float v, __nv_bfloat16& h, __nv_bfloat16& l) {
    h = __float2bfloat16_rn(v);
    l = __float2bfloat16_rn(v - __bfloat162float(h));
}
__device__ __forceinline__ void split_store4(float4 v, __nv_bfloat16* dh, __nv_bfloat16* dl) {
    __nv_bfloat16 h0,l0,h1,l1,h2,l2,h3,l3;
    split2(v.x,h0,l0); split2(v.y,h1,l1); split2(v.z,h2,l2); split2(v.w,h3,l3);
    __nv_bfloat162 p;
    p.x=h0; p.y=h1; ((__nv_bfloat162*)dh)[0]=p;
    p.x=h2; p.y=h3; ((__nv_bfloat162*)dh)[1]=p;
    p.x=l0; p.y=l1; ((__nv_bfloat162*)dl)[0]=p;
    p.x=l2; p.y=l3; ((__nv_bfloat162*)dl)[1]=p;
}

// tiny no-op kernels: keep the ncu capture window on gru_persist_kernel
__global__ void noop_kernel() {}

// ---------------------------------------------------------------------------
// prep: x split, W_hh split, W_ih split, h0/bars init, one launch
// ---------------------------------------------------------------------------
__global__ void prep_kernel(const float* __restrict__ x,
                            const float* __restrict__ W_hh,
                            const float* __restrict__ W_ih) {
    int blk = blockIdx.x, tid = threadIdx.x;
    if (blk < 32768) {
        size_t t = (size_t)blk * 256 + tid;
        size_t m = t >> 6;
        int e4 = (int)(t & 63) << 2;
        int s = (int)(m >> 9), b = (int)(m & 511);
        float4 v = *(const float4*)(x + ((size_t)b * Ssz + s) * Esz + e4);
        split_store4(v, g_x_hi + m * Esz + e4, g_x_lo + m * Esz + e4);
    } else if (blk < 33536) {
        int t = (blk - 32768) * 256 + tid;
        float4 v = *(const float4*)(W_hh + (size_t)t * 4);
        split_store4(v, g_whh_hi + (size_t)t * 4, g_whh_lo + (size_t)t * 4);
    } else if (blk < 33920) {
        int t = (blk - 33536) * 256 + tid;
        float4 v = *(const float4*)(W_ih + (size_t)t * 4);
        split_store4(v, g_wih_hi + (size_t)t * 4, g_wih_lo + (size_t)t * 4);
    } else {
        int i = (blk - 33920) * 256 + tid;   // < Bsz*Hsz/2
        __nv_bfloat162 z;
        z.x = __float2bfloat16_rn(0.0f); z.y = z.x;
        ((__nv_bfloat162*)g_hb_hi[0])[i] = z;
        ((__nv_bfloat162*)g_hb_lo[0])[i] = z;
        if (blk == 33920 && tid < 256) g_bars[tid] = 0u;
    }
}

// ---------------------------------------------------------------------------
// gi GEMM (HMMA), R14: 128x128 tile, K=256 in 8 chunks of 32, DOUBLE-buffered.
// Per chunk-buffer: A_hi/A_lo/B_hi/B_lo each 128 rows x 80B (64B data+16B pad,
// conflict-free: 8 rows at 80B stride hit 8 distinct bank-quads).
// 80KB smem -> 2 CTAs/SM. Order per chunk: wait -> sync -> issue(c+1) ->
// compute(c): single sync per chunk, chunk c+1 loads under compute c.
// K accumulation order identical to the R7/R11 gi -> bit-identical output.
// ---------------------------------------------------------------------------
#define GI_CH   40960
#define GI_SMEM (2 * GI_CH)
#define GAH 0
#define GAL 10240
#define GBH 20480
#define GBL 30720

__global__ void __launch_bounds__(256) gi_mma_kernel(const float* __restrict__ b_ih) {
    extern __shared__ __align__(16) char dsm[];
    __shared__ float s_bias[128];
    uint32_t sbase = smem_u32(dsm);
    int tid = threadIdx.x, wid = tid >> 5, lane = tid & 31;
    int n0 = blockIdx.x * 128;          // n-tiles inner for A L2 reuse
    int m0 = blockIdx.y * 128;
    if (tid < 128) s_bias[tid] = b_ih[n0 + tid];

    int m_warp = (wid & 1) * 64;
    int n_warp = (wid >> 1) * 32;

    float acc[4][4][4];
#pragma unroll
    for (int mi = 0; mi < 4; mi++)
#pragma unroll
        for (int ni = 0; ni < 4; ni++)
#pragma unroll
            for (int e = 0; e < 4; e++) acc[mi][ni][e] = 0.0f;

    auto issue = [&](int c, int q) {
        uint32_t base = sbase + (uint32_t)q * GI_CH;
        int k0 = c * 32;
        for (int i = tid; i < 2048; i += 256) {
            int arr = i >> 10;               // 0 A, 1 B
            int half = (i >> 9) & 1;         // 0 hi, 1 lo
            int idx = i & 511;
            int row = idx >> 2, seg = idx & 3;
            const __nv_bfloat16* sp;
            if (arr == 0)
                sp = (half ? g_x_lo : g_x_hi) + ((size_t)(m0 + row)) * Esz + k0 + seg * 8;
            else
                sp = (half ? g_wih_lo : g_wih_hi) + ((size_t)(n0 + row)) * Esz + k0 + seg * 8;
            uint32_t dst = base + (uint32_t)(arr * 20480 + half * 10240 + row * 80 + seg * 16);
            cp16(dst, sp);
        }
        CP_COMMIT();
    };

    issue(0, 0);
    for (int c = 0; c < 8; c++) {
        int q = c & 1;
        CP_WAIT(0);
        __syncthreads();
        if (c < 7) issue(c + 1, q ^ 1);
        uint32_t bb = sbase + (uint32_t)q * GI_CH;
#pragma unroll
        for (int kk = 0; kk < 2; kk++) {
            int kb = kk * 32;
            uint32_t fa[2][4][4];
#pragma unroll
            for (int mi = 0; mi < 4; mi++) {
                uint32_t arow = (uint32_t)(m_warp + mi * 16 + (lane & 15));
                uint32_t aoff = arow * 80 + kb + ((lane >> 4) << 4);
                LDMX4(fa[0][mi], bb + GAH + aoff);
                LDMX4(fa[1][mi], bb + GAL + aoff);
            }
            uint32_t fb[2][2][4];
#pragma unroll
            for (int p = 0; p < 2; p++) {
                uint32_t brow = (uint32_t)(n_warp + p * 16 + (lane & 7) + ((lane >> 4) << 3));
                uint32_t boff = brow * 80 + kb + (((lane >> 3) & 1) << 4);
                LDMX4(fb[0][p], bb + GBH + boff);
                LDMX4(fb[1][p], bb + GBL + boff);
            }
#pragma unroll
            for (int t = 0; t < 3; t++) {
                int sa = (t == 2) ? 1 : 0, sb = (t == 1) ? 1 : 0;
#pragma unroll
                for (int mi = 0; mi < 4; mi++)
#pragma unroll
                    for (int ni = 0; ni < 4; ni++)
                        MMA_BF16(acc[mi][ni], fa[sa][mi],
                                 fb[sb][ni >> 1][(ni & 1) * 2],
                                 fb[sb][ni >> 1][(ni & 1) * 2 + 1]);
            }
        }
    }

#pragma unroll
    for (int mi = 0; mi < 4; mi++) {
        int m = m0 + m_warp + mi * 16 + (lane >> 2);
#pragma unroll
        for (int ni = 0; ni < 4; ni++) {
            int nl = n_warp + ni * 8 + (lane & 3) * 2;
            float2 v0 = make_float2(acc[mi][ni][0] + s_bias[nl],
                                    acc[mi][ni][1] + s_bias[nl + 1]);
            float2 v1 = make_float2(acc[mi][ni][2] + s_bias[nl],
                                    acc[mi][ni][3] + s_bias[nl + 1]);
            *(float2*)(g_gi + (size_t)m * Gsz + n0 + nl) = v0;
            *(float2*)(g_gi + (size_t)(m + 8) * Gsz + n0 + nl) = v1;
        }
    }
}

// ---------------------------------------------------------------------------
// Persistent GRU recurrence — R11 CHAMPION, byte-identical.
// ---------------------------------------------------------------------------
#define WSPLIT 98304
#define WCHUNK 12288
#define WTOT   196608
#define HBUF   16384
#define HSPLIT 8192
#define PS_SMEM (WTOT + 2 * HBUF)   // 229376

__device__ __forceinline__ void prefetch_gi(int s, int brow0, int brow1, int jcol,
                                            float2 pg[3][2][2]) {
    const float* base = g_gi + (size_t)s * Bsz * Gsz;
#pragma unroll
    for (int g = 0; g < 3; g++) {
#pragma unroll
        for (int ri = 0; ri < 2; ri++) {
            const float* p = base + (size_t)(ri ? brow1 : brow0) * Gsz + g * Hsz + jcol;
            pg[g][ri][0] = *(const float2*)(p);
            pg[g][ri][1] = *(const float2*)(p + 8);
        }
    }
}

__global__ void __launch_bounds__(256) gru_persist_kernel(
    const float* __restrict__ b_hh, const float* __restrict__ W_out,
    const float* __restrict__ b_out, float* __restrict__ out) {
    extern __shared__ __align__(16) char dsm[];
    __shared__ float s_bhh[96];
    uint32_t sbase = smem_u32(dsm);
    int tid = threadIdx.x, wid = tid >> 5, lane = tid & 31;
    int bx = blockIdx.x >> 4, jy = blockIdx.x & 15;
    int b0 = bx * 64, j0 = jy * 32;
    if (tid < 96) s_bhh[tid] = b_hh[(tid >> 5) * Hsz + j0 + (tid & 31)];

    // ---- resident W_hh tile: 12288 x 16B, XOR swizzle ----
    for (int i = tid; i < 12288; i += 256) {
        int p = i / 6144;
        int ii = i - p * 6144;
        int c = ii / 768;
        int r2 = ii - c * 768;
        int r = r2 >> 3, u = r2 & 7;
        int g = r >> 5, jr = r & 31;
        const __nv_bfloat16* sp = (p ? g_whh_lo : g_whh_hi) +
            ((size_t)(g * Hsz + j0 + jr)) * Hsz + c * 64 + u * 8;
        uint32_t dst = sbase + (uint32_t)(p * WSPLIT + c * WCHUNK + r * 128 +
                                          ((u ^ (r & 7)) << 4));
        cp16(dst, sp);
    }
    CP_COMMIT();
    CP_WAIT(0);
    __syncthreads();

    const int m_warp = (wid & 3) * 16;     // 4 warps on M (64 rows)
    const int wj = wid >> 2;               // 2 warps on j (16 j's each)
    const int q2 = (lane & 3) * 2;
    const int r0 = m_warp + (lane >> 2);
    const int jb = wj * 16 + q2;
    const int brow0 = b0 + r0, brow1 = b0 + r0 + 8;
    const int jcol = j0 + jb;
    unsigned int* bar = &g_bars[bx * 32];

    // kk-invariant LDSM address parts
    const uint32_t arow = (uint32_t)(m_warp + (lane & 15));
    const uint32_t a_ub = (uint32_t)(lane >> 4);
    const uint32_t a_rowoff = arow * 128;
    const uint32_t a_rx = arow & 7;
    uint32_t b_rowoff[3], b_rx[3];
#pragma unroll
    for (int pp = 0; pp < 3; pp++) {
        uint32_t brow = (uint32_t)(pp * 32 + wj * 16 + (lane & 7) + ((lane >> 4) << 3));
        b_rowoff[pp] = brow * 128;
        b_rx[pp] = brow & 7;
    }
    const uint32_t b_ub = (uint32_t)((lane >> 3) & 1);

    float2 hp[2][2];
#pragma unroll
    for (int ri = 0; ri < 2; ri++)
#pragma unroll
        for (int su = 0; su < 2; su++) hp[ri][su] = make_float2(0.0f, 0.0f);

    float2 pg[3][2][2];
    prefetch_gi(0, brow0, brow1, jcol, pg);

    for (int s = 0; s < Ssz; s++) {
        int pin = s & 1, pout = pin ^ 1;
        const __nv_bfloat16* ah = g_hb_hi[pin];
        const __nv_bfloat16* al = g_hb_lo[pin];

        auto issue_h = [&](int c, int q) {
            uint32_t base = sbase + WTOT + (uint32_t)q * HBUF;
            for (int i = tid; i < 1024; i += 256) {
                int p = i >> 9;
                int idx = i & 511;
                int row = idx >> 3, u = idx & 7;
                const __nv_bfloat16* sp = (p ? al : ah) +
                    ((size_t)(b0 + row)) * Hsz + c * 64 + u * 8;
                uint32_t dst = base + (uint32_t)(p * HSPLIT + row * 128 +
                                                 ((u ^ (row & 7)) << 4));
                cp16(dst, sp);
            }
            CP_COMMIT();
        };

        float acc[6][4];
#pragma unroll
        for (int ni = 0; ni < 6; ni++)
#pragma unroll
            for (int e = 0; e < 4; e++) acc[ni][e] = 0.0f;

        issue_h(0, 0);
        for (int c = 0; c < 8; c++) {
            int q = c & 1;
            if (c < 7) { issue_h(c + 1, q ^ 1); CP_WAIT(1); } else { CP_WAIT(0); }
            __syncthreads();
            uint32_t hb = sbase + WTOT + (uint32_t)q * HBUF;
            uint32_t wb = sbase + (uint32_t)c * WCHUNK;

            uint32_t fa[2][2][4];
            uint32_t fb[2][2][3][4];
            auto load_frags = [&](int kk, int fq) {
                uint32_t ua = (uint32_t)(kk * 2) + a_ub;
                uint32_t offa = a_rowoff + ((ua ^ a_rx) << 4);
                LDMX4(fa[fq][0], hb + offa);
                LDMX4(fa[fq][1], hb + HSPLIT + offa);
                uint32_t ub = (uint32_t)(kk * 2) + b_ub;
#pragma unroll
                for (int pp = 0; pp < 3; pp++) {
                    uint32_t offb = b_rowoff[pp] + ((ub ^ b_rx[pp]) << 4);
                    LDMX4(fb[fq][0][pp], wb + offb);
                    LDMX4(fb[fq][1][pp], wb + WSPLIT + offb);
                }
            };

            load_frags(0, 0);
#pragma unroll
            for (int kk = 0; kk < 4; kk++) {
                int fq = kk & 1;
                if (kk < 3) load_frags(kk + 1, fq ^ 1);
#pragma unroll
                for (int t = 0; t < 3; t++) {
                    int sa = (t == 2) ? 1 : 0, sb = (t == 1) ? 1 : 0;
#pragma unroll
                    for (int ni = 0; ni < 6; ni++)
                        MMA_BF16(acc[ni], fa[fq][sa],
                                 fb[fq][sb][ni >> 1][(ni & 1) * 2],
                                 fb[fq][sb][ni >> 1][(ni & 1) * 2 + 1]);
                }
            }
        }

        // ---- register-resident GRU epilogue (fast-math sigmoid) ----
        __nv_bfloat16* hho = g_hb_hi[pout];
        __nv_bfloat16* hlo = g_hb_lo[pout];
#pragma unroll
        for (int ri = 0; ri < 2; ri++) {
            int b = ri ? brow1 : brow0;
#pragma unroll
            for (int su = 0; su < 2; su++) {
                float hv[2];
#pragma unroll
                for (int e = 0; e < 2; e++) {
                    float dr = acc[0 * 2 + su][ri * 2 + e] + s_bhh[jb + su * 8 + e];
                    float dz = acc[1 * 2 + su][ri * 2 + e] + s_bhh[32 + jb + su * 8 + e];
                    float dn = acc[2 * 2 + su][ri * 2 + e] + s_bhh[64 + jb + su * 8 + e];
                    float gi_r = e ? pg[0][ri][su].y : pg[0][ri][su].x;
                    float gi_z = e ? pg[1][ri][su].y : pg[1][ri][su].x;
                    float gi_n = e ? pg[2][ri][su].y : pg[2][ri][su].x;
                    float hprev = e ? hp[ri][su].y : hp[ri][su].x;
                    float r = __fdividef(1.0f, 1.0f + __expf(-(gi_r + dr)));
                    float z = __fdividef(1.0f, 1.0f + __expf(-(gi_z + dz)));
                    float n = tanhf(gi_n + r * dn);
                    hv[e] = (1.0f - z) * n + z * hprev;
                }
                hp[ri][su] = make_float2(hv[0], hv[1]);
                int j = jcol + su * 8;
                __nv_bfloat16 h0, l0, h1, l1;
                split2(hv[0], h0, l0);
                split2(hv[1], h1, l1);
                __nv_bfloat162 ph, pl;
                ph.x = h0; ph.y = h1;
                pl.x = l0; pl.y = l1;
                *(__nv_bfloat162*)(hho + (size_t)b * Hsz + j) = ph;
                *(__nv_bfloat162*)(hlo + (size_t)b * Hsz + j) = pl;
                if (s == Ssz - 1)
                    *(float2*)(g_hf + (size_t)b * Hsz + j) = make_float2(hv[0], hv[1]);
            }
        }

        // ---- publish FIRST (all h stores are pre-sync), then prefetch gi ----
        __syncthreads();
        if (tid == 0) {
            asm volatile("red.release.gpu.global.add.u32 [%0], %1;"
                         :: "l"(bar), "r"(1u) : "memory");
        }
        if (s + 1 < Ssz) prefetch_gi(s + 1, brow0, brow1, jcol, pg);

        // ---- per-b-group barrier wait ----
        if (tid == 0) {
            unsigned int target = (unsigned int)(s + 1) * 16u;
            unsigned int v;
            do {
                asm volatile("ld.acquire.gpu.u32 %0, [%1];" : "=r"(v) : "l"(bar));
            } while (v < target);
        }
        __syncthreads();
    }

    // ---- fused head: jy==0 CTAs compute logits+softmax for rows b0..b0+63 ----
    if (jy == 0) {
#pragma unroll 1
        for (int rr = 0; rr < 8; rr++) {
            int b = b0 + (wid << 3) + rr;
            const float* h = g_hf + (size_t)b * Hsz;
            float a8[Lsz];
#pragma unroll
            for (int l = 0; l < Lsz; l++) a8[l] = 0.0f;
            for (int j = lane; j < Hsz; j += 32) {
                float hv = h[j];
#pragma unroll
                for (int l = 0; l < Lsz; l++) a8[l] += hv * W_out[l * Hsz + j];
            }
#pragma unroll
            for (int l = 0; l < Lsz; l++)
#pragma unroll
                for (int o = 16; o > 0; o >>= 1)
                    a8[l] += __shfl_xor_sync(0xffffffff, a8[l], o);
            if (lane == 0) {
                float logits[Lsz], mx = -1e30f, sum = 0.0f;
#pragma unroll
                for (int l = 0; l < Lsz; l++) {
                    logits[l] = a8[l] + b_out[l];
                    mx = fmaxf(mx, logits[l]);
                }
#pragma unroll
                for (int l = 0; l < Lsz; l++) {
                    logits[l] = expf(logits[l] - mx);
                    sum += logits[l];
                }
                float inv = 1.0f / sum;
#pragma unroll
                for (int l = 0; l < Lsz; l++)
                    out[(size_t)b * Lsz + l] = logits[l] * inv;
            }
        }
    }
}

// ---------------------------------------------------------------------------
extern "C" void kernel_launch(void* const* d_in, const int* in_sizes, int n_in,
                              void* d_out, int out_size) {
    const float* x     = (const float*)d_in[0];
    const float* W_ih  = (const float*)d_in[1];
    const float* W_hh  = (const float*)d_in[2];
    const float* b_ih  = (const float*)d_in[3];
    const float* b_hh  = (const float*)d_in[4];
    const float* W_out = (const float*)d_in[5];
    const float* b_out = (const float*)d_in[6];
    float* out = (float*)d_out;

    cudaFuncSetAttribute(gi_mma_kernel, cudaFuncAttributeMaxDynamicSharedMemorySize, GI_SMEM);
    cudaFuncSetAttribute(gru_persist_kernel, cudaFuncAttributeMaxDynamicSharedMemorySize, PS_SMEM);

    // identical launch sequence so the ncu window stays on gru
    noop_kernel<<<1, 32>>>();
    prep_kernel<<<34432, 256>>>(x, W_hh, W_ih);
    gi_mma_kernel<<<dim3(Gsz / 128, MROWS / 128), 256, GI_SMEM>>>(b_ih);
    gru_persist_kernel<<<NCTA, 256, PS_SMEM>>>(b_hh, W_out, b_out, out);
    noop_kernel<<<1, 32>>>();
    noop_kernel<<<1, 32>>>();
}

// round 15
// speedup vs baseline: 1.1537x; 1.0159x over previous
#include <cuda_runtime.h>
#include <cuda_bf16.h>
#include <cstdint>
#include <math.h>

#define Bsz 512
#define Ssz 256
#define Esz 256
#define Hsz 512
#define Gsz 1536
#define Lsz 8
#define MROWS (Ssz * Bsz)
#define NCTA 128

// ---------------- device-global scratch (no runtime alloc) ------------------
__device__ __align__(16) float g_gi[(size_t)MROWS * Gsz];
__device__ __align__(16) float g_hf[Bsz * Hsz];          // final h only
__device__ __align__(16) __nv_bfloat16 g_hb_hi[2][Bsz * Hsz];
__device__ __align__(16) __nv_bfloat16 g_hb_lo[2][Bsz * Hsz];
__device__ __align__(16) __nv_bfloat16 g_x_hi[(size_t)MROWS * Esz];
__device__ __align__(16) __nv_bfloat16 g_x_lo[(size_t)MROWS * Esz];
__device__ __align__(16) __nv_bfloat16 g_whh_hi[Gsz * Hsz];
__device__ __align__(16) __nv_bfloat16 g_whh_lo[Gsz * Hsz];
__device__ __align__(16) __nv_bfloat16 g_wih_hi[Gsz * Esz];
__device__ __align__(16) __nv_bfloat16 g_wih_lo[Gsz * Esz];
__device__ unsigned int g_bars[8 * 32];   // per-b-group counters, 128B apart

// ---------------- PTX helpers (base-target only) -----------------------------
__device__ __forceinline__ uint32_t smem_u32(const void* p) {
    uint32_t a;
    asm("{ .reg .u64 t; cvta.to.shared.u64 t, %1; cvt.u32.u64 %0, t; }" : "=r"(a) : "l"(p));
    return a;
}
__device__ __forceinline__ void cp16(uint32_t dst, const void* src) {
    asm volatile("cp.async.cg.shared.global [%0], [%1], 16;" :: "r"(dst), "l"(src));
}
#define CP_COMMIT() asm volatile("cp.async.commit_group;" ::: "memory")
#define CP_WAIT(n)  asm volatile("cp.async.wait_group %0;" :: "n"(n) : "memory")

#define LDMX4(r, addr) \
    asm volatile("ldmatrix.sync.aligned.m8n8.x4.shared.b16 {%0,%1,%2,%3}, [%4];" \
        : "=r"((r)[0]), "=r"((r)[1]), "=r"((r)[2]), "=r"((r)[3]) : "r"(addr))

#define LDMX2(r, addr) \
    asm volatile("ldmatrix.sync.aligned.m8n8.x2.shared.b16 {%0,%1}, [%2];" \
        : "=r"((r)[0]), "=r"((r)[1]) : "r"(addr))

#define MMA_BF16(c, a, b0, b1) \
    asm volatile("mma.sync.aligned.m16n8k16.row.col.f32.bf16.bf16.f32 " \
        "{%0,%1,%2,%3}, {%4,%5,%6,%7}, {%8,%9}, {%0,%1,%2,%3};" \
        : "+f"((c)[0]), "+f"((c)[1]), "+f"((c)[2]), "+f"((c)[3]) \
        : "r"((a)[0]), "r"((a)[1]), "r"((a)[2]), "r"((a)[3]), "r"(b0), "r"(b1))

// ---------------- split helpers ----------------------------------------------
__device__ __forceinline__ void split2(float v, __nv_bfloat16& h, __nv_bfloat16& l) {
    h = __float2bfloat16_rn(v);
    l = __float2bfloat16_rn(v - __bfloat162float(h));
}
__device__ __forceinline__ void split_store4(float4 v, __nv_bfloat16* dh, __nv_bfloat16* dl) {
    __nv_bfloat16 h0,l0,h1,l1,h2,l2,h3,l3;
    split2(v.x,h0,l0); split2(v.y,h1,l1); split2(v.z,h2,l2); split2(v.w,h3,l3);
    __nv_bfloat162 p;
    p.x=h0; p.y=h1; ((__nv_bfloat162*)dh)[0]=p;
    p.x=h2; p.y=h3; ((__nv_bfloat162*)dh)[1]=p;
    p.x=l0; p.y=l1; ((__nv_bfloat162*)dl)[0]=p;
    p.x=l2; p.y=l3; ((__nv_bfloat162*)dl)[1]=p;
}

// tiny no-op kernels: keep the ncu capture window on gru_persist_kernel
__global__ void noop_kernel() {}

// ---------------------------------------------------------------------------
// prep: x split, W_hh split, W_ih split, h0/bars init, one launch
// ---------------------------------------------------------------------------
__global__ void prep_kernel(const float* __restrict__ x,
                            const float* __restrict__ W_hh,
                            const float* __restrict__ W_ih) {
    int blk = blockIdx.x, tid = threadIdx.x;
    if (blk < 32768) {
        size_t t = (size_t)blk * 256 + tid;
        size_t m = t >> 6;
        int e4 = (int)(t & 63) << 2;
        int s = (int)(m >> 9), b = (int)(m & 511);
        float4 v = *(const float4*)(x + ((size_t)b * Ssz + s) * Esz + e4);
        split_store4(v, g_x_hi + m * Esz + e4, g_x_lo + m * Esz + e4);
    } else if (blk < 33536) {
        int t = (blk - 32768) * 256 + tid;
        float4 v = *(const float4*)(W_hh + (size_t)t * 4);
        split_store4(v, g_whh_hi + (size_t)t * 4, g_whh_lo + (size_t)t * 4);
    } else if (blk < 33920) {
        int t = (blk - 33536) * 256 + tid;
        float4 v = *(const float4*)(W_ih + (size_t)t * 4);
        split_store4(v, g_wih_hi + (size_t)t * 4, g_wih_lo + (size_t)t * 4);
    } else {
        int i = (blk - 33920) * 256 + tid;   // < Bsz*Hsz/2
        __nv_bfloat162 z;
        z.x = __float2bfloat16_rn(0.0f); z.y = z.x;
        ((__nv_bfloat162*)g_hb_hi[0])[i] = z;
        ((__nv_bfloat162*)g_hb_lo[0])[i] = z;
        if (blk == 33920 && tid < 256) g_bars[tid] = 0u;
    }
}

// ---------------------------------------------------------------------------
// gi GEMM (HMMA), R14 champion: 8 chunks of K=32, double-buffered, 2 CTAs/SM.
// ---------------------------------------------------------------------------
#define GI_CH   40960
#define GI_SMEM (2 * GI_CH)
#define GAH 0
#define GAL 10240
#define GBH 20480
#define GBL 30720

__global__ void __launch_bounds__(256) gi_mma_kernel(const float* __restrict__ b_ih) {
    extern __shared__ __align__(16) char dsm[];
    __shared__ float s_bias[128];
    uint32_t sbase = smem_u32(dsm);
    int tid = threadIdx.x, wid = tid >> 5, lane = tid & 31;
    int n0 = blockIdx.x * 128;
    int m0 = blockIdx.y * 128;
    if (tid < 128) s_bias[tid] = b_ih[n0 + tid];

    int m_warp = (wid & 1) * 64;
    int n_warp = (wid >> 1) * 32;

    float acc[4][4][4];
#pragma unroll
    for (int mi = 0; mi < 4; mi++)
#pragma unroll
        for (int ni = 0; ni < 4; ni++)
#pragma unroll
            for (int e = 0; e < 4; e++) acc[mi][ni][e] = 0.0f;

    auto issue = [&](int c, int q) {
        uint32_t base = sbase + (uint32_t)q * GI_CH;
        int k0 = c * 32;
        for (int i = tid; i < 2048; i += 256) {
            int arr = i >> 10;
            int half = (i >> 9) & 1;
            int idx = i & 511;
            int row = idx >> 2, seg = idx & 3;
            const __nv_bfloat16* sp;
            if (arr == 0)
                sp = (half ? g_x_lo : g_x_hi) + ((size_t)(m0 + row)) * Esz + k0 + seg * 8;
            else
                sp = (half ? g_wih_lo : g_wih_hi) + ((size_t)(n0 + row)) * Esz + k0 + seg * 8;
            uint32_t dst = base + (uint32_t)(arr * 20480 + half * 10240 + row * 80 + seg * 16);
            cp16(dst, sp);
        }
        CP_COMMIT();
    };

    issue(0, 0);
    for (int c = 0; c < 8; c++) {
        int q = c & 1;
        CP_WAIT(0);
        __syncthreads();
        if (c < 7) issue(c + 1, q ^ 1);
        uint32_t bb = sbase + (uint32_t)q * GI_CH;
#pragma unroll
        for (int kk = 0; kk < 2; kk++) {
            int kb = kk * 32;
            uint32_t fa[2][4][4];
#pragma unroll
            for (int mi = 0; mi < 4; mi++) {
                uint32_t arow = (uint32_t)(m_warp + mi * 16 + (lane & 15));
                uint32_t aoff = arow * 80 + kb + ((lane >> 4) << 4);
                LDMX4(fa[0][mi], bb + GAH + aoff);
                LDMX4(fa[1][mi], bb + GAL + aoff);
            }
            uint32_t fb[2][2][4];
#pragma unroll
            for (int p = 0; p < 2; p++) {
                uint32_t brow = (uint32_t)(n_warp + p * 16 + (lane & 7) + ((lane >> 4) << 3));
                uint32_t boff = brow * 80 + kb + (((lane >> 3) & 1) << 4);
                LDMX4(fb[0][p], bb + GBH + boff);
                LDMX4(fb[1][p], bb + GBL + boff);
            }
#pragma unroll
            for (int t = 0; t < 3; t++) {
                int sa = (t == 2) ? 1 : 0, sb = (t == 1) ? 1 : 0;
#pragma unroll
                for (int mi = 0; mi < 4; mi++)
#pragma unroll
                    for (int ni = 0; ni < 4; ni++)
                        MMA_BF16(acc[mi][ni], fa[sa][mi],
                                 fb[sb][ni >> 1][(ni & 1) * 2],
                                 fb[sb][ni >> 1][(ni & 1) * 2 + 1]);
            }
        }
    }

#pragma unroll
    for (int mi = 0; mi < 4; mi++) {
        int m = m0 + m_warp + mi * 16 + (lane >> 2);
#pragma unroll
        for (int ni = 0; ni < 4; ni++) {
            int nl = n_warp + ni * 8 + (lane & 3) * 2;
            float2 v0 = make_float2(acc[mi][ni][0] + s_bias[nl],
                                    acc[mi][ni][1] + s_bias[nl + 1]);
            float2 v1 = make_float2(acc[mi][ni][2] + s_bias[nl],
                                    acc[mi][ni][3] + s_bias[nl + 1]);
            *(float2*)(g_gi + (size_t)m * Gsz + n0 + nl) = v0;
            *(float2*)(g_gi + (size_t)(m + 8) * Gsz + n0 + nl) = v1;
        }
    }
}

// ---------------------------------------------------------------------------
// Persistent GRU recurrence, R15:
//   (a) warp retile 4Mx2N -> 2Mx4N: wid&1 = m32 half, wid>>1 = j-quarter
//       (8 j's x 3 gates = n24/warp). B frags via ldmatrix.x2 -> B LDS bytes
//       halved; total LDS bytes/step -12.5%. Same MMA count/shape, same K
//       accumulation order -> bit-identical output.
//   (b) race-free chunk order: CP_WAIT(0) -> sync -> issue(c+1) -> compute(c).
// Everything else identical to R14 champion.
// ---------------------------------------------------------------------------
#define WSPLIT 98304
#define WCHUNK 12288
#define WTOT   196608
#define HBUF   16384
#define HSPLIT 8192
#define PS_SMEM (WTOT + 2 * HBUF)   // 229376

__global__ void __launch_bounds__(256) gru_persist_kernel(
    const float* __restrict__ b_hh, const float* __restrict__ W_out,
    const float* __restrict__ b_out, float* __restrict__ out) {
    extern __shared__ __align__(16) char dsm[];
    __shared__ float s_bhh[96];
    uint32_t sbase = smem_u32(dsm);
    int tid = threadIdx.x, wid = tid >> 5, lane = tid & 31;
    int bx = blockIdx.x >> 4, jy = blockIdx.x & 15;
    int b0 = bx * 64, j0 = jy * 32;
    if (tid < 96) s_bhh[tid] = b_hh[(tid >> 5) * Hsz + j0 + (tid & 31)];

    // ---- resident W_hh tile: 12288 x 16B, XOR swizzle (unchanged) ----
    for (int i = tid; i < 12288; i += 256) {
        int p = i / 6144;
        int ii = i - p * 6144;
        int c = ii / 768;
        int r2 = ii - c * 768;
        int r = r2 >> 3, u = r2 & 7;
        int g = r >> 5, jr = r & 31;
        const __nv_bfloat16* sp = (p ? g_whh_lo : g_whh_hi) +
            ((size_t)(g * Hsz + j0 + jr)) * Hsz + c * 64 + u * 8;
        uint32_t dst = sbase + (uint32_t)(p * WSPLIT + c * WCHUNK + r * 128 +
                                          ((u ^ (r & 7)) << 4));
        cp16(dst, sp);
    }
    CP_COMMIT();
    CP_WAIT(0);
    __syncthreads();

    // 2M x 4N warp tiling
    const int m_warp = (wid & 1) * 32;     // 2 warps on M (m32 each)
    const int jq = wid >> 1;               // 4 warps on j (8 j's each)
    const int jb = jq * 8 + (lane & 3) * 2;   // thread j cols: jb, jb+1
    const int jcol = j0 + jb;
    unsigned int* bar = &g_bars[bx * 32];

    // kk-invariant LDSM address parts
    uint32_t a_rowoff[2], a_rx[2];
#pragma unroll
    for (int mi = 0; mi < 2; mi++) {
        uint32_t arow = (uint32_t)(m_warp + mi * 16 + (lane & 15));
        a_rowoff[mi] = arow * 128;
        a_rx[mi] = arow & 7;
    }
    const uint32_t a_ub = (uint32_t)(lane >> 4);
    uint32_t b_rowoff[3], b_rx[3];
#pragma unroll
    for (int g = 0; g < 3; g++) {
        uint32_t brow = (uint32_t)(g * 32 + jq * 8 + (lane & 7));
        b_rowoff[g] = brow * 128;
        b_rx[g] = brow & 7;
    }
    const uint32_t b_ub = (uint32_t)((lane >> 3) & 1);   // lanes 0-15 matter

    // per-thread output coords: 4 rows (mi, ri), 2 j's
    float2 hp[2][2];     // h_prev carry [mi][ri]
#pragma unroll
    for (int mi = 0; mi < 2; mi++)
#pragma unroll
        for (int ri = 0; ri < 2; ri++) hp[mi][ri] = make_float2(0.0f, 0.0f);

    float2 pg[3][2][2];  // gi prefetch [gate][mi][ri]
    auto prefetch_gi = [&](int s) {
        const float* base = g_gi + (size_t)s * Bsz * Gsz;
#pragma unroll
        for (int g = 0; g < 3; g++)
#pragma unroll
            for (int mi = 0; mi < 2; mi++)
#pragma unroll
                for (int ri = 0; ri < 2; ri++) {
                    int b = b0 + m_warp + mi * 16 + ri * 8 + (lane >> 2);
                    pg[g][mi][ri] = *(const float2*)(base + (size_t)b * Gsz +
                                                     g * Hsz + jcol);
                }
    };
    prefetch_gi(0);

    for (int s = 0; s < Ssz; s++) {
        int pin = s & 1, pout = pin ^ 1;
        const __nv_bfloat16* ah = g_hb_hi[pin];
        const __nv_bfloat16* al = g_hb_lo[pin];

        auto issue_h = [&](int c, int q) {
            uint32_t base = sbase + WTOT + (uint32_t)q * HBUF;
            for (int i = tid; i < 1024; i += 256) {
                int p = i >> 9;
                int idx = i & 511;
                int row = idx >> 3, u = idx & 7;
                const __nv_bfloat16* sp = (p ? al : ah) +
                    ((size_t)(b0 + row)) * Hsz + c * 64 + u * 8;
                uint32_t dst = base + (uint32_t)(p * HSPLIT + row * 128 +
                                                 ((u ^ (row & 7)) << 4));
                cp16(dst, sp);
            }
            CP_COMMIT();
        };

        float acc[2][3][4];   // [mi][gate][4]
#pragma unroll
        for (int mi = 0; mi < 2; mi++)
#pragma unroll
            for (int g = 0; g < 3; g++)
#pragma unroll
                for (int e = 0; e < 4; e++) acc[mi][g][e] = 0.0f;

        issue_h(0, 0);
        for (int c = 0; c < 8; c++) {
            int q = c & 1;
            CP_WAIT(0);
            __syncthreads();
            if (c < 7) issue_h(c + 1, q ^ 1);   // race-free: after the sync
            uint32_t hb = sbase + WTOT + (uint32_t)q * HBUF;
            uint32_t wb = sbase + (uint32_t)c * WCHUNK;

            uint32_t fa[2][2][2][4];   // [fq][split][mi][4]
            uint32_t fb[2][2][3][2];   // [fq][split][gate][2]
            auto load_frags = [&](int kk, int fq) {
                uint32_t ua = (uint32_t)(kk * 2) + a_ub;
#pragma unroll
                for (int mi = 0; mi < 2; mi++) {
                    uint32_t offa = a_rowoff[mi] + ((ua ^ a_rx[mi]) << 4);
                    LDMX4(fa[fq][0][mi], hb + offa);
                    LDMX4(fa[fq][1][mi], hb + HSPLIT + offa);
                }
                uint32_t ub = (uint32_t)(kk * 2) + b_ub;
#pragma unroll
                for (int g = 0; g < 3; g++) {
                    uint32_t offb = b_rowoff[g] + ((ub ^ b_rx[g]) << 4);
                    LDMX2(fb[fq][0][g], wb + offb);
                    LDMX2(fb[fq][1][g], wb + WSPLIT + offb);
                }
            };

            load_frags(0, 0);
#pragma unroll
            for (int kk = 0; kk < 4; kk++) {
                int fq = kk & 1;
                if (kk < 3) load_frags(kk + 1, fq ^ 1);
#pragma unroll
                for (int t = 0; t < 3; t++) {
                    int sa = (t == 2) ? 1 : 0, sb = (t == 1) ? 1 : 0;
#pragma unroll
                    for (int mi = 0; mi < 2; mi++)
#pragma unroll
                        for (int g = 0; g < 3; g++)
                            MMA_BF16(acc[mi][g], fa[fq][sa][mi],
                                     fb[fq][sb][g][0], fb[fq][sb][g][1]);
                }
            }
        }

        // ---- register-resident GRU epilogue (fast-math sigmoid) ----
        __nv_bfloat16* hho = g_hb_hi[pout];
        __nv_bfloat16* hlo = g_hb_lo[pout];
#pragma unroll
        for (int mi = 0; mi < 2; mi++) {
#pragma unroll
            for (int ri = 0; ri < 2; ri++) {
                int b = b0 + m_warp + mi * 16 + ri * 8 + (lane >> 2);
                float hv[2];
#pragma unroll
                for (int e = 0; e < 2; e++) {
                    float dr = acc[mi][0][ri * 2 + e] + s_bhh[jb + e];
                    float dz = acc[mi][1][ri * 2 + e] + s_bhh[32 + jb + e];
                    float dn = acc[mi][2][ri * 2 + e] + s_bhh[64 + jb + e];
                    float gi_r = e ? pg[0][mi][ri].y : pg[0][mi][ri].x;
                    float gi_z = e ? pg[1][mi][ri].y : pg[1][mi][ri].x;
                    float gi_n = e ? pg[2][mi][ri].y : pg[2][mi][ri].x;
                    float hprev = e ? hp[mi][ri].y : hp[mi][ri].x;
                    float r = __fdividef(1.0f, 1.0f + __expf(-(gi_r + dr)));
                    float z = __fdividef(1.0f, 1.0f + __expf(-(gi_z + dz)));
                    float n = tanhf(gi_n + r * dn);
                    hv[e] = (1.0f - z) * n + z * hprev;
                }
                hp[mi][ri] = make_float2(hv[0], hv[1]);
                __nv_bfloat16 h0, l0, h1, l1;
                split2(hv[0], h0, l0);
                split2(hv[1], h1, l1);
                __nv_bfloat162 ph, pl;
                ph.x = h0; ph.y = h1;
                pl.x = l0; pl.y = l1;
                *(__nv_bfloat162*)(hho + (size_t)b * Hsz + jcol) = ph;
                *(__nv_bfloat162*)(hlo + (size_t)b * Hsz + jcol) = pl;
                if (s == Ssz - 1)
                    *(float2*)(g_hf + (size_t)b * Hsz + jcol) = make_float2(hv[0], hv[1]);
            }
        }

        // ---- publish FIRST, then prefetch next gi, then barrier wait ----
        __syncthreads();
        if (tid == 0) {
            asm volatile("red.release.gpu.global.add.u32 [%0], %1;"
                         :: "l"(bar), "r"(1u) : "memory");
        }
        if (s + 1 < Ssz) prefetch_gi(s + 1);

        if (tid == 0) {
            unsigned int target = (unsigned int)(s + 1) * 16u;
            unsigned int v;
            do {
                asm volatile("ld.acquire.gpu.u32 %0, [%1];" : "=r"(v) : "l"(bar));
            } while (v < target);
        }
        __syncthreads();
    }

    // ---- fused head: jy==0 CTAs compute logits+softmax for rows b0..b0+63 ----
    if (jy == 0) {
#pragma unroll 1
        for (int rr = 0; rr < 8; rr++) {
            int b = b0 + (wid << 3) + rr;
            const float* h = g_hf + (size_t)b * Hsz;
            float a8[Lsz];
#pragma unroll
            for (int l = 0; l < Lsz; l++) a8[l] = 0.0f;
            for (int j = lane; j < Hsz; j += 32) {
                float hv = h[j];
#pragma unroll
                for (int l = 0; l < Lsz; l++) a8[l] += hv * W_out[l * Hsz + j];
            }
#pragma unroll
            for (int l = 0; l < Lsz; l++)
#pragma unroll
                for (int o = 16; o > 0; o >>= 1)
                    a8[l] += __shfl_xor_sync(0xffffffff, a8[l], o);
            if (lane == 0) {
                float logits[Lsz], mx = -1e30f, sum = 0.0f;
#pragma unroll
                for (int l = 0; l < Lsz; l++) {
                    logits[l] = a8[l] + b_out[l];
                    mx = fmaxf(mx, logits[l]);
                }
#pragma unroll
                for (int l = 0; l < Lsz; l++) {
                    logits[l] = expf(logits[l] - mx);
                    sum += logits[l];
                }
                float inv = 1.0f / sum;
#pragma unroll
                for (int l = 0; l < Lsz; l++)
                    out[(size_t)b * Lsz + l] = logits[l] * inv;
            }
        }
    }
}

// ---------------------------------------------------------------------------
extern "C" void kernel_launch(void* const* d_in, const int* in_sizes, int n_in,
                              void* d_out, int out_size) {
    const float* x     = (const float*)d_in[0];
    const float* W_ih  = (const float*)d_in[1];
    const float* W_hh  = (const float*)d_in[2];
    const float* b_ih  = (const float*)d_in[3];
    const float* b_hh  = (const float*)d_in[4];
    const float* W_out = (const float*)d_in[5];
    const float* b_out = (const float*)d_in[6];
    float* out = (float*)d_out;

    cudaFuncSetAttribute(gi_mma_kernel, cudaFuncAttributeMaxDynamicSharedMemorySize, GI_SMEM);
    cudaFuncSetAttribute(gru_persist_kernel, cudaFuncAttributeMaxDynamicSharedMemorySize, PS_SMEM);

    // identical launch sequence so the ncu window stays on gru
    noop_kernel<<<1, 32>>>();
    prep_kernel<<<34432, 256>>>(x, W_hh, W_ih);
    gi_mma_kernel<<<dim3(Gsz / 128, MROWS / 128), 256, GI_SMEM>>>(b_ih);
    gru_persist_kernel<<<NCTA, 256, PS_SMEM>>>(b_hh, W_out, b_out, out);
    noop_kernel<<<1, 32>>>();
    noop_kernel<<<1, 32>>>();
}